// round 14
// baseline (speedup 1.0000x reference)
#include <cuda_runtime.h>
#include <cuda_bf16.h>
#include <math.h>
#include <stdint.h>

#define BB 128
#define LL 64
#define VV 8192
#define EE 128
#define HH 128
#define RR (BB*LL)     /* 8192 rows */
#define G4 512
#define NSTEPS 10
#define MAXBIN 512
#define KP 136         /* padded K stride in bf16 elems */
#define ROWB 272       /* KP*2 bytes per tile row */
#define LSMEM 72192    /* lstm dyn smem: 65536 W + 2048 h + 512 c + 2048 gpar + 2048 g */

typedef unsigned long long ull;
typedef unsigned int u32;

/* ------------------------------ scratch ------------------------------ */
__device__ float d_Wt[VV*EE];          /* W_visit transposed [V][E] */
__device__ float d_v[RR*EE];
__device__ float d_xg[RR*G4];
__device__ float d_h[RR*HH];
__device__ float d_hp[RR*EE];
__device__ float d_z[RR*EE];
__device__ float d_hsyn[RR*HH];
__device__ float d_TT[(NSTEPS+1)*EE];  /* temb@W_e1b^T + b_e1 per t */
__device__ int   d_len[BB];
__device__ float d_scal[2];            /* [0]=denom, [1]=loss accum */

/* bf16 hi/lo padded weight images: [hi plane Nrows*KP][lo plane Nrows*KP] */
__device__ __nv_bfloat16 d_wih_img[2*512*KP];
__device__ __nv_bfloat16 d_wproj_img[2*128*KP];
__device__ __nv_bfloat16 d_we1_img[2*128*KP];
__device__ __nv_bfloat16 d_we2_img[2*128*KP];

struct StepCoef {
    float ab[NSTEPS];
    float c1[NSTEPS + 1];
    float inva[NSTEPS + 1];
    float sb[NSTEPS + 1];
};

__device__ __forceinline__ float sigm(float x) { return 1.f / (1.f + expf(-x)); }
union F2U { ull u; float2 f; };
union F4U { float4 f; ull u[2]; };

__device__ __forceinline__ void fma2(ull& c, ull a, ull b) {
    asm("fma.rn.f32x2 %0, %1, %2, %0;" : "+l"(c) : "l"(a), "l"(b));
}

__device__ __forceinline__ u32 smem_u32(const void* p) {
    u32 a;
    asm("{ .reg .u64 t; cvta.to.shared.u64 t, %1; cvt.u32.u64 %0, t; }" : "=r"(a) : "l"(p));
    return a;
}

/* split pair of fp32 into (hi bf16x2, lo bf16x2) register images */
__device__ __forceinline__ uint2 split2(float x, float y) {
    __nv_bfloat162 h = __floats2bfloat162_rn(x, y);
    float2 hf = __bfloat1622float2(h);
    __nv_bfloat162 l = __floats2bfloat162_rn(x - hf.x, y - hf.y);
    uint2 r;
    r.x = *(u32*)&h;
    r.y = *(u32*)&l;
    return r;
}

#define MMA(c, a, b) \
    asm volatile("mma.sync.aligned.m16n8k16.row.col.f32.bf16.bf16.f32 " \
        "{%0,%1,%2,%3},{%4,%5,%6,%7},{%8,%9},{%0,%1,%2,%3};" \
        : "+f"((c)[0]), "+f"((c)[1]), "+f"((c)[2]), "+f"((c)[3]) \
        : "r"((a)[0]), "r"((a)[1]), "r"((a)[2]), "r"((a)[3]), "r"((b)[0]), "r"((b)[1]))

#define LDSM_X4(R, ADDR) \
    asm volatile("ldmatrix.sync.aligned.m8n8.x4.shared.b16 {%0,%1,%2,%3}, [%4];" \
        : "=r"((R)[0]), "=r"((R)[1]), "=r"((R)[2]), "=r"((R)[3]) : "r"(ADDR))

#define CLUSTER_SYNC() do { \
    asm volatile("barrier.cluster.arrive.aligned;" ::: "memory"); \
    asm volatile("barrier.cluster.wait.aligned;" ::: "memory"); \
} while (0)
#define CLUSTER_ARRIVE() asm volatile("barrier.cluster.arrive.aligned;" ::: "memory")
#define CLUSTER_WAIT()   asm volatile("barrier.cluster.wait.aligned;" ::: "memory")

/* ---- weight prep + W_visit transpose + prep (merged) ---------------- */
__global__ void __launch_bounds__(128)
wconv_kernel(const float* __restrict__ Wih, const float* __restrict__ Wproj,
             const float* __restrict__ We1, const float* __restrict__ We2,
             const float* __restrict__ Wvis, const float* __restrict__ mask) {
    int rb = blockIdx.x, tid = threadIdx.x;
    if (rb == 1920) {
        int b = tid;
        float s = 0.f;
        for (int l = 0; l < LL; ++l) s += mask[b * LL + l];
        int len = (int)(s + 0.5f);
        if (len < 1) len = 1;
        d_len[b] = len;
        __shared__ float red[128];
        red[b] = s;
        __syncthreads();
        for (int o = 64; o > 0; o >>= 1) { if (b < o) red[b] += red[b + o]; __syncthreads(); }
        if (b == 0) {
            float dn = red[0];
            if (dn < 1.f) dn = 1.f;
            d_scal[0] = dn;
            d_scal[1] = 0.f;
        }
        return;
    }
    if (rb >= 896) {
        __shared__ float t[32][33];
        int tb = rb - 896;
        int j0 = (tb & 255) * 32, e0 = (tb >> 8) * 32;
        int ty = tid >> 5, tx = tid & 31;
        for (int i = ty; i < 32; i += 4)
            t[i][tx] = Wvis[(size_t)(e0 + i) * VV + j0 + tx];
        __syncthreads();
        for (int i = ty; i < 32; i += 4)
            d_Wt[(size_t)(j0 + i) * EE + e0 + tx] = t[tx][i];
        return;
    }
    int k = tid;
    const float* src; int nrow, nrows; __nv_bfloat16* img; int ld = 128;
    if (rb < 512)      { src = Wih;  nrow = rb;       nrows = 512; img = d_wih_img; }
    else if (rb < 640) { src = Wproj; nrow = rb - 512; nrows = 128; img = d_wproj_img; }
    else if (rb < 768) { src = We1;  nrow = rb - 640; nrows = 128; img = d_we1_img; ld = 256; }
    else               { src = We2;  nrow = rb - 768; nrows = 128; img = d_we2_img; }
    float a = src[(size_t)nrow * ld + k];
    __nv_bfloat16 hi = __float2bfloat16(a);
    __nv_bfloat16 lo = __float2bfloat16(a - __bfloat162float(hi));
    img[(size_t)nrow * KP + k] = hi;
    img[(size_t)nrows * KP + (size_t)nrow * KP + k] = lo;
}

/* ------------------ TT table precompute (parallel) ------------------- */
__global__ void __launch_bounds__(128)
tt_kernel(const float* __restrict__ temb, const float* __restrict__ We1,
          const float* __restrict__ be1) {
    int t = blockIdx.x, j = threadIdx.x;
    const float* tr = temb + t * EE;
    const float* wr = We1 + (size_t)j * (2 * EE) + EE;
    float s = be1[j];
#pragma unroll 16
    for (int k = 0; k < EE; ++k) s += tr[k] * wr[k];
    d_TT[t * EE + j] = s;
}

/* --------------------- sparse visit embedding ------------------------ */
__global__ void __launch_bounds__(128)
compute_v_kernel(const float* __restrict__ x,
                 const int* __restrict__ bins,
                 const float* __restrict__ mask,
                 const float* __restrict__ bin_embed) {
    int row = blockIdx.x;
    int tid = threadIdx.x;
    int l = row & (LL - 1);
    float m = mask[row];
    if (m == 0.f) { d_v[(size_t)row * EE + tid] = 0.f; return; }

    int dlt = 0;
    if (l > 0) {
        dlt = bins[row] - bins[row - 1];
        if (dlt < 0) dlt = 0;
        if (dlt > MAXBIN + 1) dlt = MAXBIN + 1;
    }
    float acc = bin_embed[dlt * EE + tid];

    __shared__ int   s_idx[2048];
    __shared__ float s_val[2048];
    __shared__ int   s_cnt;
    const float4* xr4 = reinterpret_cast<const float4*>(x + (size_t)row * VV);

    for (int c0 = 0; c0 < VV; c0 += 2048) {
        if (tid == 0) s_cnt = 0;
        __syncthreads();
#pragma unroll
        for (int i = 0; i < 4; ++i) {
            int j4 = (c0 >> 2) + i * 128 + tid;
            float4 xv = xr4[j4];
            if (xv.x != 0.f) { int p = atomicAdd(&s_cnt, 1); s_idx[p] = 4*j4+0; s_val[p] = xv.x; }
            if (xv.y != 0.f) { int p = atomicAdd(&s_cnt, 1); s_idx[p] = 4*j4+1; s_val[p] = xv.y; }
            if (xv.z != 0.f) { int p = atomicAdd(&s_cnt, 1); s_idx[p] = 4*j4+2; s_val[p] = xv.z; }
            if (xv.w != 0.f) { int p = atomicAdd(&s_cnt, 1); s_idx[p] = 4*j4+3; s_val[p] = xv.w; }
        }
        __syncthreads();
        int n = s_cnt;
        for (int p = 0; p < n; ++p)
            acc += s_val[p] * d_Wt[(size_t)s_idx[p] * EE + tid];
        __syncthreads();
    }
    d_v[(size_t)row * EE + tid] = acc * m;
}

/* ------------------- generic split-bf16 HMMA GEMM -------------------- */
__global__ void __launch_bounds__(256, 2)
hmma_gemm(const float* __restrict__ A, const __nv_bfloat16* __restrict__ Wimg,
          int wlo, const float* __restrict__ bias1, const float* __restrict__ bias2,
          float* __restrict__ C, int N, int shift) {
    extern __shared__ char sm[];
    char* sAh = sm;                 /* 64*272 = 17408 */
    char* sAl = sm + 17408;
    char* sWh = sm + 34816;         /* 128*272 = 34816 */
    char* sWl = sm + 69632;
    int tid = threadIdx.x;
    int bm = blockIdx.x * 64, bn = blockIdx.y * 128;

    {
        const float4* srcH = (const float4*)(Wimg + (size_t)bn * KP);
        const float4* srcL = (const float4*)(Wimg + (size_t)wlo + (size_t)bn * KP);
        float4* dh = (float4*)sWh; float4* dl = (float4*)sWl;
        for (int i = tid; i < 2176; i += 256) { dh[i] = srcH[i]; dl[i] = srcL[i]; }
    }
    {
        int r = tid >> 2, seg = tid & 3;
        int g = bm + r;
        bool zr = shift && ((g & (LL - 1)) == 0);
        const float* arow = A + (size_t)(shift ? (g > 0 ? g - 1 : 0) : g) * EE;
#pragma unroll
        for (int k4 = 0; k4 < 8; ++k4) {
            int c = seg * 32 + k4 * 4;
            float4 f = zr ? make_float4(0.f, 0.f, 0.f, 0.f)
                          : *(const float4*)(arow + c);
            uint2 s01 = split2(f.x, f.y), s23 = split2(f.z, f.w);
            *(u32*)(sAh + r * ROWB + c * 2)     = s01.x;
            *(u32*)(sAl + r * ROWB + c * 2)     = s01.y;
            *(u32*)(sAh + r * ROWB + c * 2 + 4) = s23.x;
            *(u32*)(sAl + r * ROWB + c * 2 + 4) = s23.y;
        }
    }
    __syncthreads();

    int lane = tid & 31, w = tid >> 5;          /* 8 warps */
    int m0 = (w & 1) * 32, n0 = (w >> 1) * 32;  /* 2m x 4n warp grid */
    int gr = lane >> 2, gc = lane & 3;
    float acc[2][4][4];
#pragma unroll
    for (int i = 0; i < 2; ++i)
#pragma unroll
        for (int j = 0; j < 4; ++j)
#pragma unroll
            for (int q = 0; q < 4; ++q) acc[i][j][q] = 0.f;

    u32 aAh = smem_u32(sAh), aAl = smem_u32(sAl);
    u32 aWh = smem_u32(sWh), aWl = smem_u32(sWl);
    u32 aoff0 = (u32)((m0 + (lane & 15)) * ROWB + ((lane >> 4) & 1) * 16);
    u32 aoff1 = aoff0 + 16 * ROWB;
    u32 boff0 = (u32)((n0 + (lane & 7) + ((lane >> 4) & 1) * 8) * ROWB
                      + ((lane >> 3) & 1) * 16);
    u32 boff1 = boff0 + 16 * ROWB;

#pragma unroll
    for (int k0 = 0; k0 < 128; k0 += 16) {
        u32 kb = (u32)(k0 * 2);
        u32 ah0[4], al0[4], ah1[4], al1[4];
        u32 bh0[4], bl0[4], bh1[4], bl1[4];
        LDSM_X4(ah0, aAh + aoff0 + kb);
        LDSM_X4(al0, aAl + aoff0 + kb);
        LDSM_X4(ah1, aAh + aoff1 + kb);
        LDSM_X4(al1, aAl + aoff1 + kb);
        LDSM_X4(bh0, aWh + boff0 + kb);
        LDSM_X4(bl0, aWl + boff0 + kb);
        LDSM_X4(bh1, aWh + boff1 + kb);
        LDSM_X4(bl1, aWl + boff1 + kb);
        MMA(acc[0][0], ah0, bh0 + 0); MMA(acc[0][0], ah0, bl0 + 0); MMA(acc[0][0], al0, bh0 + 0);
        MMA(acc[0][1], ah0, bh0 + 2); MMA(acc[0][1], ah0, bl0 + 2); MMA(acc[0][1], al0, bh0 + 2);
        MMA(acc[0][2], ah0, bh1 + 0); MMA(acc[0][2], ah0, bl1 + 0); MMA(acc[0][2], al0, bh1 + 0);
        MMA(acc[0][3], ah0, bh1 + 2); MMA(acc[0][3], ah0, bl1 + 2); MMA(acc[0][3], al0, bh1 + 2);
        MMA(acc[1][0], ah1, bh0 + 0); MMA(acc[1][0], ah1, bl0 + 0); MMA(acc[1][0], al1, bh0 + 0);
        MMA(acc[1][1], ah1, bh0 + 2); MMA(acc[1][1], ah1, bl0 + 2); MMA(acc[1][1], al1, bh0 + 2);
        MMA(acc[1][2], ah1, bh1 + 0); MMA(acc[1][2], ah1, bl1 + 0); MMA(acc[1][2], al1, bh1 + 0);
        MMA(acc[1][3], ah1, bh1 + 2); MMA(acc[1][3], ah1, bl1 + 2); MMA(acc[1][3], al1, bh1 + 2);
    }

#pragma unroll
    for (int mi = 0; mi < 2; ++mi)
#pragma unroll
        for (int nt = 0; nt < 4; ++nt) {
            int col = n0 + nt * 8 + gc * 2;
            float b0 = 0.f, b1 = 0.f;
            if (bias1) {
                b0 = bias1[bn + col] + bias2[bn + col];
                b1 = bias1[bn + col + 1] + bias2[bn + col + 1];
            }
            int r0 = bm + m0 + mi * 16 + gr;
            *(float2*)&C[(size_t)r0 * N + bn + col] =
                make_float2(acc[mi][nt][0] + b0, acc[mi][nt][1] + b1);
            *(float2*)&C[(size_t)(r0 + 8) * N + bn + col] =
                make_float2(acc[mi][nt][2] + b0, acc[mi][nt][3] + b1);
        }
}

/* -------- persistent diffusion v2: barrier-free ---------------------- */
__global__ void __launch_bounds__(512, 1)
persist_diff(const float* __restrict__ z0, const float* __restrict__ noise,
             const float* __restrict__ eps, const int* __restrict__ tdiff,
             const float* __restrict__ mask, const float* __restrict__ Wf,
             const float* __restrict__ bf, const float* __restrict__ be2,
             StepCoef sc) {
    extern __shared__ char sm[];
    char*  sAh  = sm;                    /* 17408 */
    char*  sAl  = sm + 17408;
    char*  sW1h = sm + 34816;
    char*  sW1l = sm + 69632;
    char*  sW2h = sm + 104448;
    char*  sW2l = sm + 139264;
    float* s_ep = (float*)(sm + 174080); /* 64*128*4 = 32768 */
    int*   s_t  = (int*)(sm + 206848);   /* 256 */
    float* s_m  = (float*)(sm + 207104); /* 256 */
    __shared__ float s_lred[16];

    int tid = threadIdx.x, lane = tid & 31, w = tid >> 5;
    int bm = blockIdx.x * 64;

    {
        const float4* s1h = (const float4*)d_we1_img;
        const float4* s1l = (const float4*)(d_we1_img + 128 * KP);
        const float4* s2h = (const float4*)d_we2_img;
        const float4* s2l = (const float4*)(d_we2_img + 128 * KP);
        float4* d1h = (float4*)sW1h; float4* d1l = (float4*)sW1l;
        float4* d2h = (float4*)sW2h; float4* d2l = (float4*)sW2l;
        for (int i = tid; i < 2176; i += 512) {
            d1h[i] = s1h[i]; d1l[i] = s1l[i];
            d2h[i] = s2h[i]; d2l[i] = s2l[i];
        }
    }

    float bf0 = bf[0], bf1 = bf[1];
    float4 w0q = *(const float4*)&Wf[lane * 4];
    float4 w1q = *(const float4*)&Wf[128 + lane * 4];
    float4 w2q = *(const float4*)&Wf[256 + lane * 4];
    float4 w3q = *(const float4*)&Wf[384 + lane * 4];

    int m0 = (w & 3) * 16, n0 = (w >> 2) * 32;
    int gr = lane >> 2, gc = lane & 3;
    u32 aAh = smem_u32(sAh), aAl = smem_u32(sAl);
    u32 aW1h = smem_u32(sW1h), aW1l = smem_u32(sW1l);
    u32 aW2h = smem_u32(sW2h), aW2l = smem_u32(sW2l);
    u32 aoffA = (u32)((m0 + (lane & 15)) * ROWB + ((lane >> 4) & 1) * 16);
    u32 boff0 = (u32)((n0 + (lane & 7) + ((lane >> 4) & 1) * 8) * ROWB
                      + ((lane >> 3) & 1) * 16);
    u32 boff1 = boff0 + 16 * ROWB;

    float4 zr[4];

    for (int step = 0; step <= NSTEPS; ++step) {
        int kk = NSTEPS - (step - 1);

#pragma unroll 1
        for (int i = 0; i < 4; ++i) {
            int r = w * 4 + i;
            int grow = bm + r;
            float m = mask[grow];
            size_t base = (size_t)grow * EE + lane * 4;
            float4 hq = *(const float4*)&d_hp[base];
            float4 zq;
            int t;
            if (step == 0) {
                t = (m > 0.f) ? tdiff[grow >> 6] : 1;
                float ab = sc.ab[t - 1];
                float sa = sqrtf(ab) * m, sb2 = sqrtf(1.f - ab) * m;
                float4 vq = *(const float4*)&d_v[base];
                float4 eq = *(const float4*)&eps[base];
                zq.x = sa * vq.x + sb2 * eq.x;
                zq.y = sa * vq.y + sb2 * eq.y;
                zq.z = sa * vq.z + sb2 * eq.z;
                zq.w = sa * vq.w + sb2 * eq.w;
            } else if (step == 1) {
                t = (m > 0.f) ? kk : 1;
                zq = *(const float4*)&z0[base];
                zr[i] = zq;
            } else {
                t = (m > 0.f) ? kk : 1;
                int s = kk + 1;
                float4 e = *(const float4*)&s_ep[r * EE + lane * 4];
                const float* np = noise + (size_t)(NSTEPS - s) * RR * EE;
                float4 nz = *(const float4*)&np[base];
                float c1 = sc.c1[s], inva = sc.inva[s], sb2 = sc.sb[s];
                zq = zr[i];
                zq.x = ((zq.x - c1 * e.x) * inva + sb2 * nz.x) * m;
                zq.y = ((zq.y - c1 * e.y) * inva + sb2 * nz.y) * m;
                zq.z = ((zq.z - c1 * e.z) * inva + sb2 * nz.z) * m;
                zq.w = ((zq.w - c1 * e.w) * inva + sb2 * nz.w) * m;
                zr[i] = zq;
            }
            float p0 = zq.x*w0q.x + zq.y*w0q.y + zq.z*w0q.z + zq.w*w0q.w
                     + hq.x*w1q.x + hq.y*w1q.y + hq.z*w1q.z + hq.w*w1q.w;
            float p1 = zq.x*w2q.x + zq.y*w2q.y + zq.z*w2q.z + zq.w*w2q.w
                     + hq.x*w3q.x + hq.y*w3q.y + hq.z*w3q.z + hq.w*w3q.w;
#pragma unroll
            for (int o = 16; o > 0; o >>= 1) {
                p0 += __shfl_xor_sync(0xffffffffu, p0, o);
                p1 += __shfl_xor_sync(0xffffffffu, p1, o);
            }
            float a0 = 1.f / (1.f + expf((p1 + bf1) - (p0 + bf0)));
            float gx = a0 * zq.x + (1.f - a0) * hq.x;
            float gy = a0 * zq.y + (1.f - a0) * hq.y;
            float gz = a0 * zq.z + (1.f - a0) * hq.z;
            float gw = a0 * zq.w + (1.f - a0) * hq.w;
            uint2 s01 = split2(gx, gy), s23 = split2(gz, gw);
            *(u32*)(sAh + r * ROWB + lane * 8)     = s01.x;
            *(u32*)(sAl + r * ROWB + lane * 8)     = s01.y;
            *(u32*)(sAh + r * ROWB + lane * 8 + 4) = s23.x;
            *(u32*)(sAl + r * ROWB + lane * 8 + 4) = s23.y;
            if (lane == 0) { s_t[r] = t; s_m[r] = m; }
        }
        __syncthreads();

        float acc[4][4];
#pragma unroll
        for (int j = 0; j < 4; ++j)
#pragma unroll
            for (int q = 0; q < 4; ++q) acc[j][q] = 0.f;

#pragma unroll
        for (int k0 = 0; k0 < 128; k0 += 16) {
            u32 kb = (u32)(k0 * 2);
            u32 ah[4], al[4], bh0[4], bl0[4], bh1[4], bl1[4];
            LDSM_X4(ah, aAh + aoffA + kb);
            LDSM_X4(al, aAl + aoffA + kb);
            LDSM_X4(bh0, aW1h + boff0 + kb);
            LDSM_X4(bl0, aW1l + boff0 + kb);
            LDSM_X4(bh1, aW1h + boff1 + kb);
            LDSM_X4(bl1, aW1l + boff1 + kb);
            MMA(acc[0], ah, bh0 + 0); MMA(acc[0], ah, bl0 + 0); MMA(acc[0], al, bh0 + 0);
            MMA(acc[1], ah, bh0 + 2); MMA(acc[1], ah, bl0 + 2); MMA(acc[1], al, bh0 + 2);
            MMA(acc[2], ah, bh1 + 0); MMA(acc[2], ah, bl1 + 0); MMA(acc[2], al, bh1 + 0);
            MMA(acc[3], ah, bh1 + 2); MMA(acc[3], ah, bl1 + 2); MMA(acc[3], al, bh1 + 2);
        }
        __syncthreads();

#pragma unroll
        for (int nt = 0; nt < 4; ++nt) {
            int col = n0 + nt * 8 + gc * 2;
            int r0 = m0 + gr, r1 = m0 + 8 + gr;
            int t0 = s_t[r0], t1 = s_t[r1];
            float f00 = fmaxf(acc[nt][0] + d_TT[t0 * EE + col], 0.f);
            float f01 = fmaxf(acc[nt][1] + d_TT[t0 * EE + col + 1], 0.f);
            float f10 = fmaxf(acc[nt][2] + d_TT[t1 * EE + col], 0.f);
            float f11 = fmaxf(acc[nt][3] + d_TT[t1 * EE + col + 1], 0.f);
            uint2 u0 = split2(f00, f01), u1 = split2(f10, f11);
            *(u32*)(sAh + r0 * ROWB + col * 2) = u0.x;
            *(u32*)(sAl + r0 * ROWB + col * 2) = u0.y;
            *(u32*)(sAh + r1 * ROWB + col * 2) = u1.x;
            *(u32*)(sAl + r1 * ROWB + col * 2) = u1.y;
            acc[nt][0] = acc[nt][1] = acc[nt][2] = acc[nt][3] = 0.f;
        }
        __syncthreads();

#pragma unroll
        for (int k0 = 0; k0 < 128; k0 += 16) {
            u32 kb = (u32)(k0 * 2);
            u32 ah[4], al[4], bh0[4], bl0[4], bh1[4], bl1[4];
            LDSM_X4(ah, aAh + aoffA + kb);
            LDSM_X4(al, aAl + aoffA + kb);
            LDSM_X4(bh0, aW2h + boff0 + kb);
            LDSM_X4(bl0, aW2l + boff0 + kb);
            LDSM_X4(bh1, aW2h + boff1 + kb);
            LDSM_X4(bl1, aW2l + boff1 + kb);
            MMA(acc[0], ah, bh0 + 0); MMA(acc[0], ah, bl0 + 0); MMA(acc[0], al, bh0 + 0);
            MMA(acc[1], ah, bh0 + 2); MMA(acc[1], ah, bl0 + 2); MMA(acc[1], al, bh0 + 2);
            MMA(acc[2], ah, bh1 + 0); MMA(acc[2], ah, bl1 + 0); MMA(acc[2], al, bh1 + 0);
            MMA(acc[3], ah, bh1 + 2); MMA(acc[3], ah, bl1 + 2); MMA(acc[3], al, bh1 + 2);
        }

        float lsum = 0.f;
#pragma unroll
        for (int nt = 0; nt < 4; ++nt) {
            int col = n0 + nt * 8 + gc * 2;
            int r0 = m0 + gr, r1 = m0 + 8 + gr;
            float b0 = be2[col], b1 = be2[col + 1];
            float o00 = acc[nt][0] + b0, o01 = acc[nt][1] + b1;
            float o10 = acc[nt][2] + b0, o11 = acc[nt][3] + b1;
            if (step == 0) {
                float2 e0 = *(const float2*)&eps[(size_t)(bm + r0) * EE + col];
                float2 e1 = *(const float2*)&eps[(size_t)(bm + r1) * EE + col];
                float dx = o00 - e0.x, dy = o01 - e0.y;
                float dz = o10 - e1.x, dw = o11 - e1.y;
                lsum += (dx * dx + dy * dy) * s_m[r0] + (dz * dz + dw * dw) * s_m[r1];
            } else {
                *(float2*)&s_ep[r0 * EE + col] = make_float2(o00, o01);
                *(float2*)&s_ep[r1 * EE + col] = make_float2(o10, o11);
            }
        }
        if (step == 0) {
#pragma unroll
            for (int o = 16; o > 0; o >>= 1) lsum += __shfl_xor_sync(0xffffffffu, lsum, o);
            if (lane == 0) s_lred[w] = lsum;
            __syncthreads();
            if (tid == 0) {
                float s = 0.f;
                for (int i = 0; i < 16; ++i) s += s_lred[i];
                atomicAdd(&d_scal[1], s);
            }
        }
        __syncthreads();
    }

    {
        float c1 = sc.c1[1], inva = sc.inva[1];
#pragma unroll
        for (int i = 0; i < 4; ++i) {
            int r = w * 4 + i;
            float m = s_m[r];
            size_t base = (size_t)(bm + r) * EE + lane * 4;
            float4 e = *(const float4*)&s_ep[r * EE + lane * 4];
            float4 zq = zr[i];
            zq.x = (zq.x - c1 * e.x) * inva * m;
            zq.y = (zq.y - c1 * e.y) * inva * m;
            zq.z = (zq.z - c1 * e.z) * inva * m;
            zq.w = (zq.w - c1 * e.w) * inva * m;
            *(float4*)&d_z[base] = zq;
        }
    }
}

/* ------------- LSTM: cluster-of-4 split, k-split 256 threads ---------
   grid 128 = 32 clusters x 4 CTAs. CTA r owns 128 gate rows (64KB W in
   smem, [k4][row] layout). 256 thr: thread (row = tid&127, kh = tid>>7)
   computes a 64-wide half-dot for 4 batches; kh=1 partials via smem;
   kh=0 combines + adds prefetched xg. Nonlinearity on 128 thr; h quarter
   multicast to 3 peers (DSMEM); split cluster arrive/wait with next-step
   xg prefetch in between.                                               */
__global__ void __launch_bounds__(256, 1) __cluster_dims__(4, 1, 1)
lstm_kernel(const float* __restrict__ xg, const float* __restrict__ mask,
            const float* __restrict__ Whh, float* __restrict__ hout) {
    extern __shared__ char dsm[];
    float* sW    = (float*)dsm;                /* [32 k4][128 rows] f4 = 65536 */
    float* h_sh  = (float*)(dsm + 65536);      /* [4 b][128] = 2048 */
    float* c_sh  = (float*)(dsm + 67584);      /* [4 b][32]  = 512  */
    float* g_par = (float*)(dsm + 68096);      /* [4 b][128] = 2048 */
    float* g_sh  = (float*)(dsm + 70144);      /* [4 b][128] = 2048 */

    int tid = threadIdx.x;                     /* 256 */
    int row = tid & 127, kh = tid >> 7;
    u32 rank;
    asm("mov.u32 %0, %%cluster_ctarank;" : "=r"(rank));
    int r = (int)rank;
    int group = blockIdx.x >> 2;
    int g = row >> 5, ii = row & 31;
    int jglob = g * 128 + r * 32 + ii;

    /* stage W quarter: coalesced global read, [k4][row] smem layout */
    for (int idx = tid; idx < 128 * 32; idx += 256) {
        int wr = idx >> 5, k4 = idx & 31;
        int jg = ((wr >> 5) << 7) + r * 32 + (wr & 31);
        *(float4*)&sW[(k4 * 128 + wr) * 4] =
            *(const float4*)&Whh[(size_t)jg * HH + k4 * 4];
    }
    if (tid < 128) {
#pragma unroll
        for (int b = 0; b < 4; ++b) h_sh[b * 128 + tid] = 0.f;
        if (tid < 32) {
#pragma unroll
            for (int b = 0; b < 4; ++b) c_sh[b * 32 + tid] = 0.f;
        }
    }
    CLUSTER_SYNC();

    int b0 = group * 4;
    u32 peer_h[3];
    {
        u32 la = smem_u32(h_sh);
        int pi = 0;
#pragma unroll
        for (int pr = 0; pr < 4; ++pr) {
            if (pr == r) continue;
            asm("mapa.shared::cluster.u32 %0, %1, %2;" : "=r"(peer_h[pi])
                : "r"(la), "r"(pr));
            ++pi;
        }
    }

    /* xg prefetch for step 0 (kh==0 threads) */
    float xv0 = 0.f, xv1 = 0.f, xv2 = 0.f, xv3 = 0.f;
    if (kh == 0) {
        xv0 = xg[((size_t)(b0 + 0) * LL + 0) * G4 + jglob];
        xv1 = xg[((size_t)(b0 + 1) * LL + 0) * G4 + jglob];
        xv2 = xg[((size_t)(b0 + 2) * LL + 0) * G4 + jglob];
        xv3 = xg[((size_t)(b0 + 3) * LL + 0) * G4 + jglob];
    }

    int kb0 = kh * 16;
    for (int l = 0; l < LL; ++l) {
        ull a0 = 0ull, a1 = 0ull, a2 = 0ull, a3 = 0ull;
#pragma unroll 8
        for (int k4i = 0; k4i < 16; ++k4i) {
            int k4 = kb0 + k4i;
            F4U wv; wv.f = *(const float4*)&sW[(k4 * 128 + row) * 4];
            F4U h0; h0.f = *(const float4*)&h_sh[0 * 128 + k4 * 4];
            F4U h1; h1.f = *(const float4*)&h_sh[1 * 128 + k4 * 4];
            F4U h2; h2.f = *(const float4*)&h_sh[2 * 128 + k4 * 4];
            F4U h3; h3.f = *(const float4*)&h_sh[3 * 128 + k4 * 4];
            fma2(a0, wv.u[0], h0.u[0]); fma2(a0, wv.u[1], h0.u[1]);
            fma2(a1, wv.u[0], h1.u[0]); fma2(a1, wv.u[1], h1.u[1]);
            fma2(a2, wv.u[0], h2.u[0]); fma2(a2, wv.u[1], h2.u[1]);
            fma2(a3, wv.u[0], h3.u[0]); fma2(a3, wv.u[1], h3.u[1]);
        }
        F2U u0; u0.u = a0;
        F2U u1; u1.u = a1;
        F2U u2; u2.u = a2;
        F2U u3; u3.u = a3;
        float p0 = u0.f.x + u0.f.y;
        float p1 = u1.f.x + u1.f.y;
        float p2 = u2.f.x + u2.f.y;
        float p3 = u3.f.x + u3.f.y;
        if (kh == 1) {
            g_par[0 * 128 + row] = p0;
            g_par[1 * 128 + row] = p1;
            g_par[2 * 128 + row] = p2;
            g_par[3 * 128 + row] = p3;
        }
        __syncthreads();
        if (kh == 0) {
            g_sh[0 * 128 + row] = p0 + g_par[0 * 128 + row] + xv0;
            g_sh[1 * 128 + row] = p1 + g_par[1 * 128 + row] + xv1;
            g_sh[2 * 128 + row] = p2 + g_par[2 * 128 + row] + xv2;
            g_sh[3 * 128 + row] = p3 + g_par[3 * 128 + row] + xv3;
        }
        __syncthreads();

        /* nonlinearity: 128 thr = 4 batches x 32 idx */
        if (tid < 128) {
            int b2 = tid >> 5, i2 = tid & 31;
            float gi = g_sh[b2 * 128 + 0  + i2];
            float gf = g_sh[b2 * 128 + 32 + i2];
            float gg = g_sh[b2 * 128 + 64 + i2];
            float go = g_sh[b2 * 128 + 96 + i2];
            float c = sigm(gf) * c_sh[b2 * 32 + i2] + sigm(gi) * tanhf(gg);
            float h = sigm(go) * tanhf(c);
            c_sh[b2 * 32 + i2] = c;
            int off = b2 * 128 + r * 32 + i2;
            h_sh[off] = h;
#pragma unroll
            for (int pi = 0; pi < 3; ++pi)
                asm volatile("st.shared::cluster.f32 [%0], %1;"
                             :: "r"(peer_h[pi] + (u32)off * 4u), "f"(h) : "memory");
            int orow = (b0 + b2) * LL + l;
            hout[(size_t)orow * HH + r * 32 + i2] = h * mask[orow];
        }
        CLUSTER_ARRIVE();
        if (kh == 0 && l + 1 < LL) {
            xv0 = xg[((size_t)(b0 + 0) * LL + l + 1) * G4 + jglob];
            xv1 = xg[((size_t)(b0 + 1) * LL + l + 1) * G4 + jglob];
            xv2 = xg[((size_t)(b0 + 2) * LL + l + 1) * G4 + jglob];
            xv3 = xg[((size_t)(b0 + 3) * LL + l + 1) * G4 + jglob];
        }
        CLUSTER_WAIT();
    }
}

/* ------------------------------ logits ------------------------------- */
__global__ void __launch_bounds__(128)
logits_kernel(const float* __restrict__ h, const float* __restrict__ Wcls,
              const float* __restrict__ bcls, float* __restrict__ out) {
    int b = blockIdx.x, tid = threadIdx.x;
    int l = d_len[b] - 1;
    float p = h[((size_t)b * LL + l) * HH + tid] * Wcls[tid];
    __shared__ float red[128];
    red[tid] = p;
    __syncthreads();
    for (int o = 64; o > 0; o >>= 1) { if (tid < o) red[tid] += red[tid + o]; __syncthreads(); }
    if (tid == 0) out[b] = red[0] + bcls[0];
}

__global__ void __launch_bounds__(1)
final_kernel(float* __restrict__ out) {
    out[256] = d_scal[1] / d_scal[0];
}

/* ============================== host ================================= */
extern "C" void kernel_launch(void* const* d_in, const int* in_sizes, int n_in,
                              void* d_out, int out_size) {
    const float* padded_x   = (const float*)d_in[0];
    const float* visit_mask = (const float*)d_in[1];
    const int*   padded_bins= (const int*)  d_in[2];
    const int*   t_diff     = (const int*)  d_in[3];
    const float* eps        = (const float*)d_in[4];
    const float* z0         = (const float*)d_in[5];
    const float* noise      = (const float*)d_in[6];
    const float* W_visit    = (const float*)d_in[7];
    const float* bin_embed  = (const float*)d_in[8];
    const float* W_ih       = (const float*)d_in[9];
    const float* W_hh       = (const float*)d_in[10];
    const float* b_ih       = (const float*)d_in[11];
    const float* b_hh       = (const float*)d_in[12];
    const float* W_cls      = (const float*)d_in[13];
    const float* b_cls      = (const float*)d_in[14];
    const float* W_proj     = (const float*)d_in[15];
    const float* time_embed = (const float*)d_in[16];
    const float* W_fuse     = (const float*)d_in[17];
    const float* b_fuse     = (const float*)d_in[18];
    const float* W_e1       = (const float*)d_in[19];
    const float* b_e1       = (const float*)d_in[20];
    const float* W_e2       = (const float*)d_in[21];
    const float* b_e2       = (const float*)d_in[22];
    float* out = (float*)d_out;
    (void)in_sizes; (void)n_in; (void)out_size;

    float *v, *xg, *h, *hp, *z, *hsyn;
    __nv_bfloat16 *wih_img, *wproj_img;
    cudaGetSymbolAddress((void**)&v,    d_v);
    cudaGetSymbolAddress((void**)&xg,   d_xg);
    cudaGetSymbolAddress((void**)&h,    d_h);
    cudaGetSymbolAddress((void**)&hp,   d_hp);
    cudaGetSymbolAddress((void**)&z,    d_z);
    cudaGetSymbolAddress((void**)&hsyn, d_hsyn);
    cudaGetSymbolAddress((void**)&wih_img,   d_wih_img);
    cudaGetSymbolAddress((void**)&wproj_img, d_wproj_img);

    static int attr_done = 0;
    if (!attr_done) {
        cudaFuncSetAttribute(hmma_gemm,    cudaFuncAttributeMaxDynamicSharedMemorySize, 104448);
        cudaFuncSetAttribute(persist_diff, cudaFuncAttributeMaxDynamicSharedMemorySize, 207616);
        cudaFuncSetAttribute(lstm_kernel,  cudaFuncAttributeMaxDynamicSharedMemorySize, LSMEM);
        attr_done = 1;
    }

    /* diffusion schedule (host, fp64) */
    double betas[NSTEPS], alphas[NSTEPS], abars[NSTEPS];
    double prod = 1.0;
    for (int i = 0; i < NSTEPS; ++i) {
        betas[i] = 1e-4 + (double)i * (2e-2 - 1e-4) / (double)(NSTEPS - 1);
        alphas[i] = 1.0 - betas[i];
        prod *= alphas[i];
        abars[i] = prod;
    }
    StepCoef sc;
    for (int i = 0; i < NSTEPS; ++i) sc.ab[i] = (float)abars[i];
    for (int s = 1; s <= NSTEPS; ++s) {
        sc.c1[s]   = (float)(betas[s - 1] / sqrt(1.0 - abars[s - 1]));
        sc.inva[s] = (float)(1.0 / sqrt(alphas[s - 1]));
        sc.sb[s]   = (float)sqrt(betas[s - 1]);
    }
    sc.c1[0] = sc.inva[0] = sc.sb[0] = 0.f;

    /* ---- pipeline (idx 3 = lstm, profiled) ---- */
    wconv_kernel<<<1921, 128>>>(W_ih, W_proj, W_e1, W_e2, W_visit, visit_mask);    /* 0 */
    compute_v_kernel<<<RR, 128>>>(padded_x, padded_bins, visit_mask, bin_embed);   /* 1 */
    hmma_gemm<<<dim3(RR / 64, 4), 256, 104448>>>(v, wih_img, 512 * KP,
                b_ih, b_hh, xg, G4, 0);                                            /* 2 */
    lstm_kernel<<<128, 256, LSMEM>>>(xg, visit_mask, W_hh, h);                     /* 3 */

    tt_kernel<<<NSTEPS + 1, 128>>>(time_embed, W_e1, b_e1);
    logits_kernel<<<BB, 128>>>(h, W_cls, b_cls, out);

    /* hp = shift(h) @ W_proj^T */
    hmma_gemm<<<dim3(RR / 64, 1), 256, 104448>>>(h, wproj_img, 128 * KP,
                0, 0, hp, EE, 1);

    /* all 11 diffusion steps, barrier-free persistent kernel */
    persist_diff<<<RR / 64, 512, 207616>>>(z0, noise, eps, t_diff, visit_mask,
                                           W_fuse, b_fuse, b_e2, sc);

    /* encoder LSTM on synthetic data (persist wrote final z) */
    hmma_gemm<<<dim3(RR / 64, 4), 256, 104448>>>(z, wih_img, 512 * KP,
                b_ih, b_hh, xg, G4, 0);
    lstm_kernel<<<128, 256, LSMEM>>>(xg, visit_mask, W_hh, hsyn);
    logits_kernel<<<BB, 128>>>(hsyn, W_cls, b_cls, out + 128);

    final_kernel<<<1, 1>>>(out);
}

// round 15
// speedup vs baseline: 1.0940x; 1.0940x over previous
#include <cuda_runtime.h>
#include <cuda_bf16.h>
#include <math.h>
#include <stdint.h>

#define BB 128
#define LL 64
#define VV 8192
#define EE 128
#define HH 128
#define RR (BB*LL)     /* 8192 rows */
#define G4 512
#define NSTEPS 10
#define MAXBIN 512
#define KP 136         /* padded K stride in bf16 elems */
#define ROWB 272       /* KP*2 bytes per tile row */
#define LSMEM 74368    /* lstm dyn smem */

typedef unsigned long long ull;
typedef unsigned int u32;

/* ------------------------------ scratch ------------------------------ */
__device__ float d_Wt[VV*EE];          /* W_visit transposed [V][E] */
__device__ float d_v[RR*EE];
__device__ float d_xg[RR*G4];
__device__ float d_h[RR*HH];
__device__ float d_hp[RR*EE];
__device__ float d_z[RR*EE];
__device__ float d_hsyn[RR*HH];
__device__ float d_TT[(NSTEPS+1)*EE];  /* temb@W_e1b^T + b_e1 per t */
__device__ int   d_len[BB];
__device__ float d_scal[2];            /* [0]=denom, [1]=loss accum */

/* bf16 hi/lo padded weight images: [hi plane Nrows*KP][lo plane Nrows*KP] */
__device__ __nv_bfloat16 d_wih_img[2*512*KP];
__device__ __nv_bfloat16 d_wproj_img[2*128*KP];
__device__ __nv_bfloat16 d_we1_img[2*128*KP];
__device__ __nv_bfloat16 d_we2_img[2*128*KP];

struct StepCoef {
    float ab[NSTEPS];
    float c1[NSTEPS + 1];
    float inva[NSTEPS + 1];
    float sb[NSTEPS + 1];
};

__device__ __forceinline__ float sigm(float x) { return 1.f / (1.f + expf(-x)); }
union F2U { ull u; float2 f; };
union F4U { float4 f; ull u[2]; };

__device__ __forceinline__ void fma2(ull& c, ull a, ull b) {
    asm("fma.rn.f32x2 %0, %1, %2, %0;" : "+l"(c) : "l"(a), "l"(b));
}

__device__ __forceinline__ u32 smem_u32(const void* p) {
    u32 a;
    asm("{ .reg .u64 t; cvta.to.shared.u64 t, %1; cvt.u32.u64 %0, t; }" : "=r"(a) : "l"(p));
    return a;
}

/* split pair of fp32 into (hi bf16x2, lo bf16x2) register images */
__device__ __forceinline__ uint2 split2(float x, float y) {
    __nv_bfloat162 h = __floats2bfloat162_rn(x, y);
    float2 hf = __bfloat1622float2(h);
    __nv_bfloat162 l = __floats2bfloat162_rn(x - hf.x, y - hf.y);
    uint2 r;
    r.x = *(u32*)&h;
    r.y = *(u32*)&l;
    return r;
}

#define MMA(c, a, b) \
    asm volatile("mma.sync.aligned.m16n8k16.row.col.f32.bf16.bf16.f32 " \
        "{%0,%1,%2,%3},{%4,%5,%6,%7},{%8,%9},{%0,%1,%2,%3};" \
        : "+f"((c)[0]), "+f"((c)[1]), "+f"((c)[2]), "+f"((c)[3]) \
        : "r"((a)[0]), "r"((a)[1]), "r"((a)[2]), "r"((a)[3]), "r"((b)[0]), "r"((b)[1]))

#define LDSM_X4(R, ADDR) \
    asm volatile("ldmatrix.sync.aligned.m8n8.x4.shared.b16 {%0,%1,%2,%3}, [%4];" \
        : "=r"((R)[0]), "=r"((R)[1]), "=r"((R)[2]), "=r"((R)[3]) : "r"(ADDR))

#define CLUSTER_SYNC() do { \
    asm volatile("barrier.cluster.arrive.aligned;" ::: "memory"); \
    asm volatile("barrier.cluster.wait.aligned;" ::: "memory"); \
} while (0)

/* wait on local mbarrier, cluster-scope acquire */
__device__ __forceinline__ void mb_waitc(u32 mb, u32 parity) {
    asm volatile(
        "{\n\t.reg .pred P1;\n\t"
        "WAIT_LOOP_%=:\n\t"
        "mbarrier.try_wait.parity.acquire.cluster.shared::cta.b64 P1, [%0], %1, 0x989680;\n\t"
        "@P1 bra.uni WAIT_DONE_%=;\n\t"
        "bra.uni WAIT_LOOP_%=;\n\t"
        "WAIT_DONE_%=:\n\t}"
        :: "r"(mb), "r"(parity) : "memory");
}

/* ---- weight prep + W_visit transpose + prep (merged) ---------------- */
__global__ void __launch_bounds__(128)
wconv_kernel(const float* __restrict__ Wih, const float* __restrict__ Wproj,
             const float* __restrict__ We1, const float* __restrict__ We2,
             const float* __restrict__ Wvis, const float* __restrict__ mask) {
    int rb = blockIdx.x, tid = threadIdx.x;
    if (rb == 1920) {
        int b = tid;
        float s = 0.f;
        for (int l = 0; l < LL; ++l) s += mask[b * LL + l];
        int len = (int)(s + 0.5f);
        if (len < 1) len = 1;
        d_len[b] = len;
        __shared__ float red[128];
        red[b] = s;
        __syncthreads();
        for (int o = 64; o > 0; o >>= 1) { if (b < o) red[b] += red[b + o]; __syncthreads(); }
        if (b == 0) {
            float dn = red[0];
            if (dn < 1.f) dn = 1.f;
            d_scal[0] = dn;
            d_scal[1] = 0.f;
        }
        return;
    }
    if (rb >= 896) {
        __shared__ float t[32][33];
        int tb = rb - 896;
        int j0 = (tb & 255) * 32, e0 = (tb >> 8) * 32;
        int ty = tid >> 5, tx = tid & 31;
        for (int i = ty; i < 32; i += 4)
            t[i][tx] = Wvis[(size_t)(e0 + i) * VV + j0 + tx];
        __syncthreads();
        for (int i = ty; i < 32; i += 4)
            d_Wt[(size_t)(j0 + i) * EE + e0 + tx] = t[tx][i];
        return;
    }
    int k = tid;
    const float* src; int nrow, nrows; __nv_bfloat16* img; int ld = 128;
    if (rb < 512)      { src = Wih;  nrow = rb;       nrows = 512; img = d_wih_img; }
    else if (rb < 640) { src = Wproj; nrow = rb - 512; nrows = 128; img = d_wproj_img; }
    else if (rb < 768) { src = We1;  nrow = rb - 640; nrows = 128; img = d_we1_img; ld = 256; }
    else               { src = We2;  nrow = rb - 768; nrows = 128; img = d_we2_img; }
    float a = src[(size_t)nrow * ld + k];
    __nv_bfloat16 hi = __float2bfloat16(a);
    __nv_bfloat16 lo = __float2bfloat16(a - __bfloat162float(hi));
    img[(size_t)nrow * KP + k] = hi;
    img[(size_t)nrows * KP + (size_t)nrow * KP + k] = lo;
}

/* ------------------ TT table precompute (parallel) ------------------- */
__global__ void __launch_bounds__(128)
tt_kernel(const float* __restrict__ temb, const float* __restrict__ We1,
          const float* __restrict__ be1) {
    int t = blockIdx.x, j = threadIdx.x;
    const float* tr = temb + t * EE;
    const float* wr = We1 + (size_t)j * (2 * EE) + EE;
    float s = be1[j];
#pragma unroll 16
    for (int k = 0; k < EE; ++k) s += tr[k] * wr[k];
    d_TT[t * EE + j] = s;
}

/* --------------------- sparse visit embedding ------------------------ */
__global__ void __launch_bounds__(128)
compute_v_kernel(const float* __restrict__ x,
                 const int* __restrict__ bins,
                 const float* __restrict__ mask,
                 const float* __restrict__ bin_embed) {
    int row = blockIdx.x;
    int tid = threadIdx.x;
    int l = row & (LL - 1);
    float m = mask[row];
    if (m == 0.f) { d_v[(size_t)row * EE + tid] = 0.f; return; }

    int dlt = 0;
    if (l > 0) {
        dlt = bins[row] - bins[row - 1];
        if (dlt < 0) dlt = 0;
        if (dlt > MAXBIN + 1) dlt = MAXBIN + 1;
    }
    float acc = bin_embed[dlt * EE + tid];

    __shared__ int   s_idx[2048];
    __shared__ float s_val[2048];
    __shared__ int   s_cnt;
    const float4* xr4 = reinterpret_cast<const float4*>(x + (size_t)row * VV);

    for (int c0 = 0; c0 < VV; c0 += 2048) {
        if (tid == 0) s_cnt = 0;
        __syncthreads();
#pragma unroll
        for (int i = 0; i < 4; ++i) {
            int j4 = (c0 >> 2) + i * 128 + tid;
            float4 xv = xr4[j4];
            if (xv.x != 0.f) { int p = atomicAdd(&s_cnt, 1); s_idx[p] = 4*j4+0; s_val[p] = xv.x; }
            if (xv.y != 0.f) { int p = atomicAdd(&s_cnt, 1); s_idx[p] = 4*j4+1; s_val[p] = xv.y; }
            if (xv.z != 0.f) { int p = atomicAdd(&s_cnt, 1); s_idx[p] = 4*j4+2; s_val[p] = xv.z; }
            if (xv.w != 0.f) { int p = atomicAdd(&s_cnt, 1); s_idx[p] = 4*j4+3; s_val[p] = xv.w; }
        }
        __syncthreads();
        int n = s_cnt;
        for (int p = 0; p < n; ++p)
            acc += s_val[p] * d_Wt[(size_t)s_idx[p] * EE + tid];
        __syncthreads();
    }
    d_v[(size_t)row * EE + tid] = acc * m;
}

/* ------------------- generic split-bf16 HMMA GEMM -------------------- */
__global__ void __launch_bounds__(256, 2)
hmma_gemm(const float* __restrict__ A, const __nv_bfloat16* __restrict__ Wimg,
          int wlo, const float* __restrict__ bias1, const float* __restrict__ bias2,
          float* __restrict__ C, int N, int shift) {
    extern __shared__ char sm[];
    char* sAh = sm;                 /* 64*272 = 17408 */
    char* sAl = sm + 17408;
    char* sWh = sm + 34816;         /* 128*272 = 34816 */
    char* sWl = sm + 69632;
    int tid = threadIdx.x;
    int bm = blockIdx.x * 64, bn = blockIdx.y * 128;

    {
        const float4* srcH = (const float4*)(Wimg + (size_t)bn * KP);
        const float4* srcL = (const float4*)(Wimg + (size_t)wlo + (size_t)bn * KP);
        float4* dh = (float4*)sWh; float4* dl = (float4*)sWl;
        for (int i = tid; i < 2176; i += 256) { dh[i] = srcH[i]; dl[i] = srcL[i]; }
    }
    {
        int r = tid >> 2, seg = tid & 3;
        int g = bm + r;
        bool zr = shift && ((g & (LL - 1)) == 0);
        const float* arow = A + (size_t)(shift ? (g > 0 ? g - 1 : 0) : g) * EE;
#pragma unroll
        for (int k4 = 0; k4 < 8; ++k4) {
            int c = seg * 32 + k4 * 4;
            float4 f = zr ? make_float4(0.f, 0.f, 0.f, 0.f)
                          : *(const float4*)(arow + c);
            uint2 s01 = split2(f.x, f.y), s23 = split2(f.z, f.w);
            *(u32*)(sAh + r * ROWB + c * 2)     = s01.x;
            *(u32*)(sAl + r * ROWB + c * 2)     = s01.y;
            *(u32*)(sAh + r * ROWB + c * 2 + 4) = s23.x;
            *(u32*)(sAl + r * ROWB + c * 2 + 4) = s23.y;
        }
    }
    __syncthreads();

    int lane = tid & 31, w = tid >> 5;          /* 8 warps */
    int m0 = (w & 1) * 32, n0 = (w >> 1) * 32;  /* 2m x 4n warp grid */
    int gr = lane >> 2, gc = lane & 3;
    float acc[2][4][4];
#pragma unroll
    for (int i = 0; i < 2; ++i)
#pragma unroll
        for (int j = 0; j < 4; ++j)
#pragma unroll
            for (int q = 0; q < 4; ++q) acc[i][j][q] = 0.f;

    u32 aAh = smem_u32(sAh), aAl = smem_u32(sAl);
    u32 aWh = smem_u32(sWh), aWl = smem_u32(sWl);
    u32 aoff0 = (u32)((m0 + (lane & 15)) * ROWB + ((lane >> 4) & 1) * 16);
    u32 aoff1 = aoff0 + 16 * ROWB;
    u32 boff0 = (u32)((n0 + (lane & 7) + ((lane >> 4) & 1) * 8) * ROWB
                      + ((lane >> 3) & 1) * 16);
    u32 boff1 = boff0 + 16 * ROWB;

#pragma unroll
    for (int k0 = 0; k0 < 128; k0 += 16) {
        u32 kb = (u32)(k0 * 2);
        u32 ah0[4], al0[4], ah1[4], al1[4];
        u32 bh0[4], bl0[4], bh1[4], bl1[4];
        LDSM_X4(ah0, aAh + aoff0 + kb);
        LDSM_X4(al0, aAl + aoff0 + kb);
        LDSM_X4(ah1, aAh + aoff1 + kb);
        LDSM_X4(al1, aAl + aoff1 + kb);
        LDSM_X4(bh0, aWh + boff0 + kb);
        LDSM_X4(bl0, aWl + boff0 + kb);
        LDSM_X4(bh1, aWh + boff1 + kb);
        LDSM_X4(bl1, aWl + boff1 + kb);
        MMA(acc[0][0], ah0, bh0 + 0); MMA(acc[0][0], ah0, bl0 + 0); MMA(acc[0][0], al0, bh0 + 0);
        MMA(acc[0][1], ah0, bh0 + 2); MMA(acc[0][1], ah0, bl0 + 2); MMA(acc[0][1], al0, bh0 + 2);
        MMA(acc[0][2], ah0, bh1 + 0); MMA(acc[0][2], ah0, bl1 + 0); MMA(acc[0][2], al0, bh1 + 0);
        MMA(acc[0][3], ah0, bh1 + 2); MMA(acc[0][3], ah0, bl1 + 2); MMA(acc[0][3], al0, bh1 + 2);
        MMA(acc[1][0], ah1, bh0 + 0); MMA(acc[1][0], ah1, bl0 + 0); MMA(acc[1][0], al1, bh0 + 0);
        MMA(acc[1][1], ah1, bh0 + 2); MMA(acc[1][1], ah1, bl0 + 2); MMA(acc[1][1], al1, bh0 + 2);
        MMA(acc[1][2], ah1, bh1 + 0); MMA(acc[1][2], ah1, bl1 + 0); MMA(acc[1][2], al1, bh1 + 0);
        MMA(acc[1][3], ah1, bh1 + 2); MMA(acc[1][3], ah1, bl1 + 2); MMA(acc[1][3], al1, bh1 + 2);
    }

#pragma unroll
    for (int mi = 0; mi < 2; ++mi)
#pragma unroll
        for (int nt = 0; nt < 4; ++nt) {
            int col = n0 + nt * 8 + gc * 2;
            float b0 = 0.f, b1 = 0.f;
            if (bias1) {
                b0 = bias1[bn + col] + bias2[bn + col];
                b1 = bias1[bn + col + 1] + bias2[bn + col + 1];
            }
            int r0 = bm + m0 + mi * 16 + gr;
            *(float2*)&C[(size_t)r0 * N + bn + col] =
                make_float2(acc[mi][nt][0] + b0, acc[mi][nt][1] + b1);
            *(float2*)&C[(size_t)(r0 + 8) * N + bn + col] =
                make_float2(acc[mi][nt][2] + b0, acc[mi][nt][3] + b1);
        }
}

/* -------- persistent diffusion v2: barrier-free ---------------------- */
__global__ void __launch_bounds__(512, 1)
persist_diff(const float* __restrict__ z0, const float* __restrict__ noise,
             const float* __restrict__ eps, const int* __restrict__ tdiff,
             const float* __restrict__ mask, const float* __restrict__ Wf,
             const float* __restrict__ bf, const float* __restrict__ be2,
             StepCoef sc) {
    extern __shared__ char sm[];
    char*  sAh  = sm;                    /* 17408 */
    char*  sAl  = sm + 17408;
    char*  sW1h = sm + 34816;
    char*  sW1l = sm + 69632;
    char*  sW2h = sm + 104448;
    char*  sW2l = sm + 139264;
    float* s_ep = (float*)(sm + 174080); /* 64*128*4 = 32768 */
    int*   s_t  = (int*)(sm + 206848);   /* 256 */
    float* s_m  = (float*)(sm + 207104); /* 256 */
    __shared__ float s_lred[16];

    int tid = threadIdx.x, lane = tid & 31, w = tid >> 5;
    int bm = blockIdx.x * 64;

    {
        const float4* s1h = (const float4*)d_we1_img;
        const float4* s1l = (const float4*)(d_we1_img + 128 * KP);
        const float4* s2h = (const float4*)d_we2_img;
        const float4* s2l = (const float4*)(d_we2_img + 128 * KP);
        float4* d1h = (float4*)sW1h; float4* d1l = (float4*)sW1l;
        float4* d2h = (float4*)sW2h; float4* d2l = (float4*)sW2l;
        for (int i = tid; i < 2176; i += 512) {
            d1h[i] = s1h[i]; d1l[i] = s1l[i];
            d2h[i] = s2h[i]; d2l[i] = s2l[i];
        }
    }

    float bf0 = bf[0], bf1 = bf[1];
    float4 w0q = *(const float4*)&Wf[lane * 4];
    float4 w1q = *(const float4*)&Wf[128 + lane * 4];
    float4 w2q = *(const float4*)&Wf[256 + lane * 4];
    float4 w3q = *(const float4*)&Wf[384 + lane * 4];

    int m0 = (w & 3) * 16, n0 = (w >> 2) * 32;
    int gr = lane >> 2, gc = lane & 3;
    u32 aAh = smem_u32(sAh), aAl = smem_u32(sAl);
    u32 aW1h = smem_u32(sW1h), aW1l = smem_u32(sW1l);
    u32 aW2h = smem_u32(sW2h), aW2l = smem_u32(sW2l);
    u32 aoffA = (u32)((m0 + (lane & 15)) * ROWB + ((lane >> 4) & 1) * 16);
    u32 boff0 = (u32)((n0 + (lane & 7) + ((lane >> 4) & 1) * 8) * ROWB
                      + ((lane >> 3) & 1) * 16);
    u32 boff1 = boff0 + 16 * ROWB;

    float4 zr[4];

    for (int step = 0; step <= NSTEPS; ++step) {
        int kk = NSTEPS - (step - 1);

#pragma unroll 1
        for (int i = 0; i < 4; ++i) {
            int r = w * 4 + i;
            int grow = bm + r;
            float m = mask[grow];
            size_t base = (size_t)grow * EE + lane * 4;
            float4 hq = *(const float4*)&d_hp[base];
            float4 zq;
            int t;
            if (step == 0) {
                t = (m > 0.f) ? tdiff[grow >> 6] : 1;
                float ab = sc.ab[t - 1];
                float sa = sqrtf(ab) * m, sb2 = sqrtf(1.f - ab) * m;
                float4 vq = *(const float4*)&d_v[base];
                float4 eq = *(const float4*)&eps[base];
                zq.x = sa * vq.x + sb2 * eq.x;
                zq.y = sa * vq.y + sb2 * eq.y;
                zq.z = sa * vq.z + sb2 * eq.z;
                zq.w = sa * vq.w + sb2 * eq.w;
            } else if (step == 1) {
                t = (m > 0.f) ? kk : 1;
                zq = *(const float4*)&z0[base];
                zr[i] = zq;
            } else {
                t = (m > 0.f) ? kk : 1;
                int s = kk + 1;
                float4 e = *(const float4*)&s_ep[r * EE + lane * 4];
                const float* np = noise + (size_t)(NSTEPS - s) * RR * EE;
                float4 nz = *(const float4*)&np[base];
                float c1 = sc.c1[s], inva = sc.inva[s], sb2 = sc.sb[s];
                zq = zr[i];
                zq.x = ((zq.x - c1 * e.x) * inva + sb2 * nz.x) * m;
                zq.y = ((zq.y - c1 * e.y) * inva + sb2 * nz.y) * m;
                zq.z = ((zq.z - c1 * e.z) * inva + sb2 * nz.z) * m;
                zq.w = ((zq.w - c1 * e.w) * inva + sb2 * nz.w) * m;
                zr[i] = zq;
            }
            float p0 = zq.x*w0q.x + zq.y*w0q.y + zq.z*w0q.z + zq.w*w0q.w
                     + hq.x*w1q.x + hq.y*w1q.y + hq.z*w1q.z + hq.w*w1q.w;
            float p1 = zq.x*w2q.x + zq.y*w2q.y + zq.z*w2q.z + zq.w*w2q.w
                     + hq.x*w3q.x + hq.y*w3q.y + hq.z*w3q.z + hq.w*w3q.w;
#pragma unroll
            for (int o = 16; o > 0; o >>= 1) {
                p0 += __shfl_xor_sync(0xffffffffu, p0, o);
                p1 += __shfl_xor_sync(0xffffffffu, p1, o);
            }
            float a0 = 1.f / (1.f + expf((p1 + bf1) - (p0 + bf0)));
            float gx = a0 * zq.x + (1.f - a0) * hq.x;
            float gy = a0 * zq.y + (1.f - a0) * hq.y;
            float gz = a0 * zq.z + (1.f - a0) * hq.z;
            float gw = a0 * zq.w + (1.f - a0) * hq.w;
            uint2 s01 = split2(gx, gy), s23 = split2(gz, gw);
            *(u32*)(sAh + r * ROWB + lane * 8)     = s01.x;
            *(u32*)(sAl + r * ROWB + lane * 8)     = s01.y;
            *(u32*)(sAh + r * ROWB + lane * 8 + 4) = s23.x;
            *(u32*)(sAl + r * ROWB + lane * 8 + 4) = s23.y;
            if (lane == 0) { s_t[r] = t; s_m[r] = m; }
        }
        __syncthreads();

        float acc[4][4];
#pragma unroll
        for (int j = 0; j < 4; ++j)
#pragma unroll
            for (int q = 0; q < 4; ++q) acc[j][q] = 0.f;

#pragma unroll
        for (int k0 = 0; k0 < 128; k0 += 16) {
            u32 kb = (u32)(k0 * 2);
            u32 ah[4], al[4], bh0[4], bl0[4], bh1[4], bl1[4];
            LDSM_X4(ah, aAh + aoffA + kb);
            LDSM_X4(al, aAl + aoffA + kb);
            LDSM_X4(bh0, aW1h + boff0 + kb);
            LDSM_X4(bl0, aW1l + boff0 + kb);
            LDSM_X4(bh1, aW1h + boff1 + kb);
            LDSM_X4(bl1, aW1l + boff1 + kb);
            MMA(acc[0], ah, bh0 + 0); MMA(acc[0], ah, bl0 + 0); MMA(acc[0], al, bh0 + 0);
            MMA(acc[1], ah, bh0 + 2); MMA(acc[1], ah, bl0 + 2); MMA(acc[1], al, bh0 + 2);
            MMA(acc[2], ah, bh1 + 0); MMA(acc[2], ah, bl1 + 0); MMA(acc[2], al, bh1 + 0);
            MMA(acc[3], ah, bh1 + 2); MMA(acc[3], ah, bl1 + 2); MMA(acc[3], al, bh1 + 2);
        }
        __syncthreads();

#pragma unroll
        for (int nt = 0; nt < 4; ++nt) {
            int col = n0 + nt * 8 + gc * 2;
            int r0 = m0 + gr, r1 = m0 + 8 + gr;
            int t0 = s_t[r0], t1 = s_t[r1];
            float f00 = fmaxf(acc[nt][0] + d_TT[t0 * EE + col], 0.f);
            float f01 = fmaxf(acc[nt][1] + d_TT[t0 * EE + col + 1], 0.f);
            float f10 = fmaxf(acc[nt][2] + d_TT[t1 * EE + col], 0.f);
            float f11 = fmaxf(acc[nt][3] + d_TT[t1 * EE + col + 1], 0.f);
            uint2 u0 = split2(f00, f01), u1 = split2(f10, f11);
            *(u32*)(sAh + r0 * ROWB + col * 2) = u0.x;
            *(u32*)(sAl + r0 * ROWB + col * 2) = u0.y;
            *(u32*)(sAh + r1 * ROWB + col * 2) = u1.x;
            *(u32*)(sAl + r1 * ROWB + col * 2) = u1.y;
            acc[nt][0] = acc[nt][1] = acc[nt][2] = acc[nt][3] = 0.f;
        }
        __syncthreads();

#pragma unroll
        for (int k0 = 0; k0 < 128; k0 += 16) {
            u32 kb = (u32)(k0 * 2);
            u32 ah[4], al[4], bh0[4], bl0[4], bh1[4], bl1[4];
            LDSM_X4(ah, aAh + aoffA + kb);
            LDSM_X4(al, aAl + aoffA + kb);
            LDSM_X4(bh0, aW2h + boff0 + kb);
            LDSM_X4(bl0, aW2l + boff0 + kb);
            LDSM_X4(bh1, aW2h + boff1 + kb);
            LDSM_X4(bl1, aW2l + boff1 + kb);
            MMA(acc[0], ah, bh0 + 0); MMA(acc[0], ah, bl0 + 0); MMA(acc[0], al, bh0 + 0);
            MMA(acc[1], ah, bh0 + 2); MMA(acc[1], ah, bl0 + 2); MMA(acc[1], al, bh0 + 2);
            MMA(acc[2], ah, bh1 + 0); MMA(acc[2], ah, bl1 + 0); MMA(acc[2], al, bh1 + 0);
            MMA(acc[3], ah, bh1 + 2); MMA(acc[3], ah, bl1 + 2); MMA(acc[3], al, bh1 + 2);
        }

        float lsum = 0.f;
#pragma unroll
        for (int nt = 0; nt < 4; ++nt) {
            int col = n0 + nt * 8 + gc * 2;
            int r0 = m0 + gr, r1 = m0 + 8 + gr;
            float b0 = be2[col], b1 = be2[col + 1];
            float o00 = acc[nt][0] + b0, o01 = acc[nt][1] + b1;
            float o10 = acc[nt][2] + b0, o11 = acc[nt][3] + b1;
            if (step == 0) {
                float2 e0 = *(const float2*)&eps[(size_t)(bm + r0) * EE + col];
                float2 e1 = *(const float2*)&eps[(size_t)(bm + r1) * EE + col];
                float dx = o00 - e0.x, dy = o01 - e0.y;
                float dz = o10 - e1.x, dw = o11 - e1.y;
                lsum += (dx * dx + dy * dy) * s_m[r0] + (dz * dz + dw * dw) * s_m[r1];
            } else {
                *(float2*)&s_ep[r0 * EE + col] = make_float2(o00, o01);
                *(float2*)&s_ep[r1 * EE + col] = make_float2(o10, o11);
            }
        }
        if (step == 0) {
#pragma unroll
            for (int o = 16; o > 0; o >>= 1) lsum += __shfl_xor_sync(0xffffffffu, lsum, o);
            if (lane == 0) s_lred[w] = lsum;
            __syncthreads();
            if (tid == 0) {
                float s = 0.f;
                for (int i = 0; i < 16; ++i) s += s_lred[i];
                atomicAdd(&d_scal[1], s);
            }
        }
        __syncthreads();
    }

    {
        float c1 = sc.c1[1], inva = sc.inva[1];
#pragma unroll
        for (int i = 0; i < 4; ++i) {
            int r = w * 4 + i;
            float m = s_m[r];
            size_t base = (size_t)(bm + r) * EE + lane * 4;
            float4 e = *(const float4*)&s_ep[r * EE + lane * 4];
            float4 zq = zr[i];
            zq.x = (zq.x - c1 * e.x) * inva * m;
            zq.y = (zq.y - c1 * e.y) * inva * m;
            zq.z = (zq.z - c1 * e.z) * inva * m;
            zq.w = (zq.w - c1 * e.w) * inva * m;
            *(float4*)&d_z[base] = zq;
        }
    }
}

/* ------------- LSTM: cluster-of-4, k-split, mbarrier sync ------------
   grid 128 = 32 clusters x 4 CTAs. CTA r owns 128 gate rows (64KB W in
   smem, [k4][row]). 256 thr (row, khalf): half-dot for 4 batches; kh=1
   partials via smem; kh=0 combines + prefetched xg. Nonlinearity on 128
   thr; h quarter stored into all 4 CTAs' DOUBLE-BUFFERED h_sh (parity
   l+1); peers signalled via mbarrier.arrive (count=3), awaited by
   try_wait.parity.acquire.cluster (~90cyc vs ~490 cluster barrier).    */
__global__ void __launch_bounds__(256, 1) __cluster_dims__(4, 1, 1)
lstm_kernel(const float* __restrict__ xg, const float* __restrict__ mask,
            const float* __restrict__ Whh, float* __restrict__ hout) {
    extern __shared__ char dsm[];
    float* sW    = (float*)dsm;                /* [32 k4][128 rows] f4 = 65536 */
    float* h_sh  = (float*)(dsm + 65536);      /* [2 buf][4 b][128] = 4096 */
    float* c_sh  = (float*)(dsm + 69632);      /* [4 b][32] = 512 */
    float* g_par = (float*)(dsm + 70144);      /* [4 b][128] = 2048 */
    float* g_sh  = (float*)(dsm + 72192);      /* [4 b][128] = 2048 */
    ull*   mbar  = (ull*)(dsm + 74240);        /* 8 */

    int tid = threadIdx.x;                     /* 256 */
    int row = tid & 127, kh = tid >> 7;
    u32 rank;
    asm("mov.u32 %0, %%cluster_ctarank;" : "=r"(rank));
    int r = (int)rank;
    int group = blockIdx.x >> 2;
    int g = row >> 5, ii = row & 31;
    int jglob = g * 128 + r * 32 + ii;

    /* stage W quarter: coalesced global read, [k4][row] smem layout */
    for (int idx = tid; idx < 128 * 32; idx += 256) {
        int wr = idx >> 5, k4 = idx & 31;
        int jg = ((wr >> 5) << 7) + r * 32 + (wr & 31);
        *(float4*)&sW[(k4 * 128 + wr) * 4] =
            *(const float4*)&Whh[(size_t)jg * HH + k4 * 4];
    }
    if (tid < 128) {
#pragma unroll
        for (int b = 0; b < 4; ++b) h_sh[b * 128 + tid] = 0.f;   /* buf 0 */
        if (tid < 32) {
#pragma unroll
            for (int b = 0; b < 4; ++b) c_sh[b * 32 + tid] = 0.f;
        }
    }
    if (tid == 0) {
        asm volatile("mbarrier.init.shared.b64 [%0], %1;"
                     :: "r"(smem_u32(mbar)), "r"(3u) : "memory");
    }
    CLUSTER_SYNC();

    int b0 = group * 4;
    u32 peer_hb[3], peer_mb[3];
    {
        u32 lh = smem_u32(h_sh), lm = smem_u32(mbar);
        int pi = 0;
#pragma unroll
        for (int pr = 0; pr < 4; ++pr) {
            if (pr == r) continue;
            asm("mapa.shared::cluster.u32 %0, %1, %2;" : "=r"(peer_hb[pi])
                : "r"(lh), "r"(pr));
            asm("mapa.shared::cluster.u32 %0, %1, %2;" : "=r"(peer_mb[pi])
                : "r"(lm), "r"(pr));
            ++pi;
        }
    }
    u32 my_mb = smem_u32(mbar);

    float xv0 = 0.f, xv1 = 0.f, xv2 = 0.f, xv3 = 0.f;
    if (kh == 0) {
        xv0 = xg[((size_t)(b0 + 0) * LL + 0) * G4 + jglob];
        xv1 = xg[((size_t)(b0 + 1) * LL + 0) * G4 + jglob];
        xv2 = xg[((size_t)(b0 + 2) * LL + 0) * G4 + jglob];
        xv3 = xg[((size_t)(b0 + 3) * LL + 0) * G4 + jglob];
    }

    int kb0 = kh * 16;
    for (int l = 0; l < LL; ++l) {
        const float* hb = h_sh + (l & 1) * 512;
        ull a0 = 0ull, a1 = 0ull, a2 = 0ull, a3 = 0ull;
#pragma unroll 8
        for (int k4i = 0; k4i < 16; ++k4i) {
            int k4 = kb0 + k4i;
            F4U wv; wv.f = *(const float4*)&sW[(k4 * 128 + row) * 4];
            F4U h0; h0.f = *(const float4*)&hb[0 * 128 + k4 * 4];
            F4U h1; h1.f = *(const float4*)&hb[1 * 128 + k4 * 4];
            F4U h2; h2.f = *(const float4*)&hb[2 * 128 + k4 * 4];
            F4U h3; h3.f = *(const float4*)&hb[3 * 128 + k4 * 4];
            fma2(a0, wv.u[0], h0.u[0]); fma2(a0, wv.u[1], h0.u[1]);
            fma2(a1, wv.u[0], h1.u[0]); fma2(a1, wv.u[1], h1.u[1]);
            fma2(a2, wv.u[0], h2.u[0]); fma2(a2, wv.u[1], h2.u[1]);
            fma2(a3, wv.u[0], h3.u[0]); fma2(a3, wv.u[1], h3.u[1]);
        }
        F2U u0; u0.u = a0;
        F2U u1; u1.u = a1;
        F2U u2; u2.u = a2;
        F2U u3; u3.u = a3;
        float p0 = u0.f.x + u0.f.y;
        float p1 = u1.f.x + u1.f.y;
        float p2 = u2.f.x + u2.f.y;
        float p3 = u3.f.x + u3.f.y;
        if (kh == 1) {
            g_par[0 * 128 + row] = p0;
            g_par[1 * 128 + row] = p1;
            g_par[2 * 128 + row] = p2;
            g_par[3 * 128 + row] = p3;
        }
        __syncthreads();
        if (kh == 0) {
            g_sh[0 * 128 + row] = p0 + g_par[0 * 128 + row] + xv0;
            g_sh[1 * 128 + row] = p1 + g_par[1 * 128 + row] + xv1;
            g_sh[2 * 128 + row] = p2 + g_par[2 * 128 + row] + xv2;
            g_sh[3 * 128 + row] = p3 + g_par[3 * 128 + row] + xv3;
        }
        __syncthreads();

        /* nonlinearity: 128 thr = 4 batches x 32 idx; write to parity buf */
        if (tid < 128) {
            int b2 = tid >> 5, i2 = tid & 31;
            float gi = g_sh[b2 * 128 + 0  + i2];
            float gf = g_sh[b2 * 128 + 32 + i2];
            float gg = g_sh[b2 * 128 + 64 + i2];
            float go = g_sh[b2 * 128 + 96 + i2];
            float c = sigm(gf) * c_sh[b2 * 32 + i2] + sigm(gi) * tanhf(gg);
            float h = sigm(go) * tanhf(c);
            c_sh[b2 * 32 + i2] = c;
            u32 off = (u32)(((l + 1) & 1) * 512 + b2 * 128 + r * 32 + i2);
            h_sh[off] = h;
#pragma unroll
            for (int pi = 0; pi < 3; ++pi)
                asm volatile("st.shared::cluster.f32 [%0], %1;"
                             :: "r"(peer_hb[pi] + off * 4u), "f"(h) : "memory");
            int orow = (b0 + b2) * LL + l;
            hout[(size_t)orow * HH + r * 32 + i2] = h * mask[orow];
        }
        __syncthreads();
        if (l + 1 < LL) {
            if (tid == 0) {
#pragma unroll
                for (int pi = 0; pi < 3; ++pi)
                    asm volatile("mbarrier.arrive.shared::cluster.b64 _, [%0];"
                                 :: "r"(peer_mb[pi]) : "memory");
            }
            if (kh == 0) {
                xv0 = xg[((size_t)(b0 + 0) * LL + l + 1) * G4 + jglob];
                xv1 = xg[((size_t)(b0 + 1) * LL + l + 1) * G4 + jglob];
                xv2 = xg[((size_t)(b0 + 2) * LL + l + 1) * G4 + jglob];
                xv3 = xg[((size_t)(b0 + 3) * LL + l + 1) * G4 + jglob];
            }
            mb_waitc(my_mb, (u32)(l & 1));
        }
    }
    CLUSTER_SYNC();
}

/* ------------------------------ logits ------------------------------- */
__global__ void __launch_bounds__(128)
logits_kernel(const float* __restrict__ h, const float* __restrict__ Wcls,
              const float* __restrict__ bcls, float* __restrict__ out) {
    int b = blockIdx.x, tid = threadIdx.x;
    int l = d_len[b] - 1;
    float p = h[((size_t)b * LL + l) * HH + tid] * Wcls[tid];
    __shared__ float red[128];
    red[tid] = p;
    __syncthreads();
    for (int o = 64; o > 0; o >>= 1) { if (tid < o) red[tid] += red[tid + o]; __syncthreads(); }
    if (tid == 0) out[b] = red[0] + bcls[0];
}

__global__ void __launch_bounds__(1)
final_kernel(float* __restrict__ out) {
    out[256] = d_scal[1] / d_scal[0];
}

/* ============================== host ================================= */
extern "C" void kernel_launch(void* const* d_in, const int* in_sizes, int n_in,
                              void* d_out, int out_size) {
    const float* padded_x   = (const float*)d_in[0];
    const float* visit_mask = (const float*)d_in[1];
    const int*   padded_bins= (const int*)  d_in[2];
    const int*   t_diff     = (const int*)  d_in[3];
    const float* eps        = (const float*)d_in[4];
    const float* z0         = (const float*)d_in[5];
    const float* noise      = (const float*)d_in[6];
    const float* W_visit    = (const float*)d_in[7];
    const float* bin_embed  = (const float*)d_in[8];
    const float* W_ih       = (const float*)d_in[9];
    const float* W_hh       = (const float*)d_in[10];
    const float* b_ih       = (const float*)d_in[11];
    const float* b_hh       = (const float*)d_in[12];
    const float* W_cls      = (const float*)d_in[13];
    const float* b_cls      = (const float*)d_in[14];
    const float* W_proj     = (const float*)d_in[15];
    const float* time_embed = (const float*)d_in[16];
    const float* W_fuse     = (const float*)d_in[17];
    const float* b_fuse     = (const float*)d_in[18];
    const float* W_e1       = (const float*)d_in[19];
    const float* b_e1       = (const float*)d_in[20];
    const float* W_e2       = (const float*)d_in[21];
    const float* b_e2       = (const float*)d_in[22];
    float* out = (float*)d_out;
    (void)in_sizes; (void)n_in; (void)out_size;

    float *v, *xg, *h, *hp, *z, *hsyn;
    __nv_bfloat16 *wih_img, *wproj_img;
    cudaGetSymbolAddress((void**)&v,    d_v);
    cudaGetSymbolAddress((void**)&xg,   d_xg);
    cudaGetSymbolAddress((void**)&h,    d_h);
    cudaGetSymbolAddress((void**)&hp,   d_hp);
    cudaGetSymbolAddress((void**)&z,    d_z);
    cudaGetSymbolAddress((void**)&hsyn, d_hsyn);
    cudaGetSymbolAddress((void**)&wih_img,   d_wih_img);
    cudaGetSymbolAddress((void**)&wproj_img, d_wproj_img);

    static int attr_done = 0;
    if (!attr_done) {
        cudaFuncSetAttribute(hmma_gemm,    cudaFuncAttributeMaxDynamicSharedMemorySize, 104448);
        cudaFuncSetAttribute(persist_diff, cudaFuncAttributeMaxDynamicSharedMemorySize, 207616);
        cudaFuncSetAttribute(lstm_kernel,  cudaFuncAttributeMaxDynamicSharedMemorySize, LSMEM);
        attr_done = 1;
    }

    /* diffusion schedule (host, fp64) */
    double betas[NSTEPS], alphas[NSTEPS], abars[NSTEPS];
    double prod = 1.0;
    for (int i = 0; i < NSTEPS; ++i) {
        betas[i] = 1e-4 + (double)i * (2e-2 - 1e-4) / (double)(NSTEPS - 1);
        alphas[i] = 1.0 - betas[i];
        prod *= alphas[i];
        abars[i] = prod;
    }
    StepCoef sc;
    for (int i = 0; i < NSTEPS; ++i) sc.ab[i] = (float)abars[i];
    for (int s = 1; s <= NSTEPS; ++s) {
        sc.c1[s]   = (float)(betas[s - 1] / sqrt(1.0 - abars[s - 1]));
        sc.inva[s] = (float)(1.0 / sqrt(alphas[s - 1]));
        sc.sb[s]   = (float)sqrt(betas[s - 1]);
    }
    sc.c1[0] = sc.inva[0] = sc.sb[0] = 0.f;

    /* ---- pipeline (idx 3 = lstm, profiled) ---- */
    wconv_kernel<<<1921, 128>>>(W_ih, W_proj, W_e1, W_e2, W_visit, visit_mask);    /* 0 */
    compute_v_kernel<<<RR, 128>>>(padded_x, padded_bins, visit_mask, bin_embed);   /* 1 */
    hmma_gemm<<<dim3(RR / 64, 4), 256, 104448>>>(v, wih_img, 512 * KP,
                b_ih, b_hh, xg, G4, 0);                                            /* 2 */
    lstm_kernel<<<128, 256, LSMEM>>>(xg, visit_mask, W_hh, h);                     /* 3 */

    tt_kernel<<<NSTEPS + 1, 128>>>(time_embed, W_e1, b_e1);
    logits_kernel<<<BB, 128>>>(h, W_cls, b_cls, out);

    /* hp = shift(h) @ W_proj^T */
    hmma_gemm<<<dim3(RR / 64, 1), 256, 104448>>>(h, wproj_img, 128 * KP,
                0, 0, hp, EE, 1);

    /* all 11 diffusion steps, barrier-free persistent kernel */
    persist_diff<<<RR / 64, 512, 207616>>>(z0, noise, eps, t_diff, visit_mask,
                                           W_fuse, b_fuse, b_e2, sc);

    /* encoder LSTM on synthetic data (persist wrote final z) */
    hmma_gemm<<<dim3(RR / 64, 4), 256, 104448>>>(z, wih_img, 512 * KP,
                b_ih, b_hh, xg, G4, 0);
    lstm_kernel<<<128, 256, LSMEM>>>(xg, visit_mask, W_hh, hsyn);
    logits_kernel<<<BB, 128>>>(hsyn, W_cls, b_cls, out + 128);

    final_kernel<<<1, 1>>>(out);
}